// round 16
// baseline (speedup 1.0000x reference)
#include <cuda_runtime.h>
#include <cuda_fp16.h>
#include <cstdint>

// ---------------------------------------------------------------------------
// Problem constants
// ---------------------------------------------------------------------------
#define N_WORD   30000
#define N_TOPIC  1000
#define N_DOC    15000
#define D_IN     300
#define D_OUT    128

#define E_WW 800000
#define E_WT 400000
#define E_WD 600000
#define E_TD 300000
#define E_TT 150000
#define E_TOT (E_WW + E_WT + E_WD + E_TD + E_TT)   // 2,250,000
// etype ids: 0=ww, 1=wt, 2=wd, 3=td, 4=tt (all boundaries divisible by 4)

// 8-way replicated degree counters: deg[dst*8 + rep], rep = thread gid & 7.
// Cuts per-address atomic serialization 8x; per-dst segment in the pair
// array remains contiguous: [off[d*8], off[d*8+8]).
#define REP  8

// GEMM tile bookkeeping. Tile order: ww(235) | wd(235), td(8) | wt(235), tt(8)
#define T_W  235
#define T_T  8
#define TILES_WW   T_W                              // 235
#define TILES_WDTD (T_W + T_T)                      // 243
#define TILES_G2   (TILES_WW + TILES_WDTD)          // 478
#define TILES_TOTAL (3 * T_W + 2 * T_T)             // 721
#define KCH  32
#define NCH  10

// ---------------------------------------------------------------------------
// Static device scratch.  Wh in fp16 (agg math stays fp32).
// ---------------------------------------------------------------------------
__device__ __half g_Wh_ww[(size_t)N_WORD  * D_OUT];
__device__ __half g_Wh_wt[(size_t)N_WORD  * D_OUT];
__device__ __half g_Wh_wd[(size_t)N_WORD  * D_OUT];
__device__ __half g_Wh_td[(size_t)N_TOPIC * D_OUT];
__device__ __half g_Wh_tt[(size_t)N_TOPIC * D_OUT];

__device__ __align__(16) int g_deg_ww[N_WORD  * REP]; __device__ int g_off_ww[N_WORD  * REP + 1];
__device__ __align__(16) int g_deg_wt[N_TOPIC * REP]; __device__ int g_off_wt[N_TOPIC * REP + 1];
__device__ __align__(16) int g_deg_wd[N_DOC   * REP]; __device__ int g_off_wd[N_DOC   * REP + 1];
__device__ __align__(16) int g_deg_td[N_DOC   * REP]; __device__ int g_off_td[N_DOC   * REP + 1];
__device__ __align__(16) int g_deg_tt[N_TOPIC * REP]; __device__ int g_off_tt[N_TOPIC * REP + 1];

__device__ __align__(16) int g_rank[E_TOT];

__device__ uint2 g_pair_ww[E_WW];
__device__ uint2 g_pair_wt[E_WT];
__device__ uint2 g_pair_wd[E_WD];
__device__ uint2 g_pair_td[E_TD];
__device__ uint2 g_pair_tt[E_TT];

__device__ __forceinline__ __half* Wh_ptr(int et) {
    switch (et) { case 0: return g_Wh_ww; case 1: return g_Wh_wt; case 2: return g_Wh_wd;
                  case 3: return g_Wh_td; default: return g_Wh_tt; }
}
__device__ __forceinline__ int* deg_ptr(int et) {
    switch (et) { case 0: return g_deg_ww; case 1: return g_deg_wt; case 2: return g_deg_wd;
                  case 3: return g_deg_td; default: return g_deg_tt; }
}
__device__ __forceinline__ int* off_ptr(int et) {
    switch (et) { case 0: return g_off_ww; case 1: return g_off_wt; case 2: return g_off_wd;
                  case 3: return g_off_td; default: return g_off_tt; }
}
__device__ __forceinline__ uint2* pair_ptr(int et) {
    switch (et) { case 0: return g_pair_ww; case 1: return g_pair_wt; case 2: return g_pair_wd;
                  case 3: return g_pair_td; default: return g_pair_tt; }
}
__device__ __forceinline__ int ndst_of(int et) {
    switch (et) { case 0: return N_WORD; case 1: return N_TOPIC; case 2: return N_DOC;
                  case 3: return N_DOC; default: return N_TOPIC; }
}

__device__ __forceinline__ float4 ldWh4(const __half* Wh, unsigned src, int lane) {
    uint2 raw = *(const uint2*)(Wh + (size_t)src * D_OUT + lane * 4);
    __half2 h0 = *reinterpret_cast<__half2*>(&raw.x);
    __half2 h1 = *reinterpret_cast<__half2*>(&raw.y);
    float2 f0 = __half22float2(h0);
    float2 f1 = __half22float2(h1);
    return make_float4(f0.x, f0.y, f1.x, f1.y);
}

// ---------------------------------------------------------------------------
// Pointer bundles
// ---------------------------------------------------------------------------
struct EdgeArgs {
    const int*   src[5];
    const int*   dst[5];
    const float* w[5];
};
struct GemmArgs {
    const float* featW;
    const float* featT;
    const float* Wm[5];
    const float* bias[5];
};

__device__ __forceinline__ void edge_map(int i, int& et, int& j) {
    if (i < E_WW)                        { et = 0; j = i; }
    else if (i < E_WW + E_WT)            { et = 1; j = i - E_WW; }
    else if (i < E_WW + E_WT + E_WD)     { et = 2; j = i - (E_WW + E_WT); }
    else if (i < E_TOT - E_TT)           { et = 3; j = i - (E_WW + E_WT + E_WD); }
    else                                 { et = 4; j = i - (E_TOT - E_TT); }
}

// ---------------------------------------------------------------------------
// Kernel 2: fused histogram into replicated counters; atomic return = rank
// within the (dst, rep) bucket. deg[] zeroed by previous call's scan.
// ---------------------------------------------------------------------------
__global__ void hist_all_kernel(EdgeArgs ea) {
    int gid = blockIdx.x * blockDim.x + threadIdx.x;
    int i4 = gid * 4;
    if (i4 >= E_TOT) return;
    int rep = gid & (REP - 1);
    int et, j; edge_map(i4, et, j);
    int* deg = deg_ptr(et);
    int4 d4 = *(const int4*)(ea.dst[et] + j);
    int4 r4;
    r4.x = atomicAdd(&deg[d4.x * REP + rep], 1);
    r4.y = atomicAdd(&deg[d4.y * REP + rep], 1);
    r4.z = atomicAdd(&deg[d4.z * REP + rep], 1);
    r4.w = atomicAdd(&deg[d4.w * REP + rep], 1);
    *(int4*)(g_rank + i4) = r4;
}

// ---------------------------------------------------------------------------
// Kernel 3: fused scan over the flattened (dst*REP + rep) degree arrays,
// one block per etype. Re-zeroes deg during the sum pass (dead afterwards).
// ---------------------------------------------------------------------------
__global__ void scan_all_kernel() {
    const int et = blockIdx.x;
    const int n8 = ndst_of(et) * REP;
    int* deg = deg_ptr(et);
    int* off = off_ptr(et);
    __shared__ int warp_pre[32];
    __shared__ int s_total;

    const int t = threadIdx.x;
    const int lane = t & 31, wid = t >> 5;
    int chunk = (((n8 + 1023) >> 10) + 3) & ~3;
    int beg = t * chunk;
    int end = min(beg + chunk, n8);

    // phase 1: per-thread sum + re-zero
    int s = 0;
    const int4 z4 = make_int4(0, 0, 0, 0);
    int i = beg;
    for (; i + 4 <= end; i += 4) {
        int4 v = *(const int4*)(deg + i);
        s += v.x + v.y + v.z + v.w;
    }
    for (; i < end; i++) s += deg[i];

    // block scan of per-thread sums
    int inc = s;
#pragma unroll
    for (int d = 1; d < 32; d <<= 1) {
        int v = __shfl_up_sync(0xFFFFFFFFu, inc, d);
        if (lane >= d) inc += v;
    }
    if (lane == 31) warp_pre[wid] = inc;
    __syncthreads();
    if (wid == 0) {
        int ws = warp_pre[lane];
        int winc = ws;
#pragma unroll
        for (int d = 1; d < 32; d <<= 1) {
            int v = __shfl_up_sync(0xFFFFFFFFu, winc, d);
            if (lane >= d) winc += v;
        }
        warp_pre[lane] = winc - ws;
        if (lane == 31) s_total = winc;
    }
    __syncthreads();

    // phase 2: write offsets (deg L2-hot), then zero deg
    int run = warp_pre[wid] + (inc - s);
    for (int j2 = beg; j2 < end; j2++) {
        off[j2] = run;
        run += deg[j2];
    }
    if (t == 0) off[n8] = s_total;
    // zero after use
    i = beg;
    for (; i + 4 <= end; i += 4) *(int4*)(deg + i) = z4;
    for (; i < end; i++) deg[i] = 0;
}

// ---------------------------------------------------------------------------
// Kernel 4: atomic-free fill, 4 edges/thread; rep must match hist's rep
// ---------------------------------------------------------------------------
__global__ void fill_all_kernel(EdgeArgs ea) {
    int gid = blockIdx.x * blockDim.x + threadIdx.x;
    int i4 = gid * 4;
    if (i4 >= E_TOT) return;
    int rep = gid & (REP - 1);
    int et, j; edge_map(i4, et, j);
    const int* off = off_ptr(et);
    uint2* pp = pair_ptr(et);
    int4   s4 = *(const int4*)(ea.src[et] + j);
    int4   d4 = *(const int4*)(ea.dst[et] + j);
    float4 w4 = *(const float4*)(ea.w[et] + j);
    int4   r4 = *(const int4*)(g_rank + i4);

    pp[off[d4.x * REP + rep] + r4.x] = make_uint2((unsigned)s4.x, __float_as_uint(w4.x));
    pp[off[d4.y * REP + rep] + r4.y] = make_uint2((unsigned)s4.y, __float_as_uint(w4.y));
    pp[off[d4.z * REP + rep] + r4.z] = make_uint2((unsigned)s4.z, __float_as_uint(w4.z));
    pp[off[d4.w * REP + rep] + r4.w] = make_uint2((unsigned)s4.w, __float_as_uint(w4.w));
}

// ---------------------------------------------------------------------------
// Kernel 5: tf32 GEMM, cp.async double-buffered, fp16 epilogue.
// Tile order: ww(0..234), wd(235..469), td(470..477), wt(478..712), tt(713..720)
// ---------------------------------------------------------------------------
__device__ __forceinline__ unsigned f2tf32(float x) {
    unsigned u; asm("cvt.rna.tf32.f32 %0, %1;" : "=r"(u) : "f"(x)); return u;
}
__device__ __forceinline__ void mma_tf32(float* c, const unsigned* a, const unsigned* b) {
    asm volatile(
        "mma.sync.aligned.m16n8k8.row.col.f32.tf32.tf32.f32 "
        "{%0,%1,%2,%3}, {%4,%5,%6,%7}, {%8,%9}, {%0,%1,%2,%3};\n"
        : "+f"(c[0]), "+f"(c[1]), "+f"(c[2]), "+f"(c[3])
        : "r"(a[0]), "r"(a[1]), "r"(a[2]), "r"(a[3]), "r"(b[0]), "r"(b[1]));
}
__device__ __forceinline__ void cp_async16(void* smem, const void* gmem, int valid_bytes) {
    unsigned sa = (unsigned)__cvta_generic_to_shared(smem);
    asm volatile("cp.async.cg.shared.global [%0], [%1], 16, %2;\n"
                 :: "r"(sa), "l"(gmem), "r"(valid_bytes));
}

__global__ void __launch_bounds__(256, 2)
gemm_tf32_kernel(GemmArgs ga, int bt0) {
    __shared__ float Af[2][128][36];
    __shared__ float Bf[2][32][136];

    int bt = blockIdx.x + bt0;
    int et, tile;
    if      (bt < T_W)                 { et = 0; tile = bt; }
    else if (bt < 2 * T_W)             { et = 2; tile = bt - T_W; }
    else if (bt < TILES_G2)            { et = 3; tile = bt - 2 * T_W; }
    else if (bt < TILES_G2 + T_W)      { et = 1; tile = bt - TILES_G2; }
    else                               { et = 4; tile = bt - (TILES_G2 + T_W); }

    const float* A    = (et < 3) ? ga.featW : ga.featT;
    const int    M    = (et < 3) ? N_WORD : N_TOPIC;
    const float* Wm   = ga.Wm[et];
    const float* bias = ga.bias[et];
    __half*      C    = Wh_ptr(et);

    const int row0 = tile * 128;
    const int tid  = threadIdx.x;
    const int lane = tid & 31, wid = tid >> 5;
    const int wm = wid & 3, wn = wid >> 2;
    const int g  = lane >> 2, tg = lane & 3;

    float acc[2][8][4];
#pragma unroll
    for (int mi = 0; mi < 2; mi++)
#pragma unroll
        for (int ni = 0; ni < 8; ni++)
#pragma unroll
            for (int q = 0; q < 4; q++) acc[mi][ni][q] = 0.0f;

    auto load_chunk = [&](int k0, int buf) {
#pragma unroll
        for (int it = 0; it < 4; it++) {
            int slot = it * 256 + tid;
            int r = slot >> 3, kq = slot & 7;
            int gr = row0 + r, gk = k0 + kq * 4;
            int ok = (gr < M && gk + 4 <= D_IN);
            const float* gp = A + (size_t)(ok ? gr : 0) * D_IN + (ok ? gk : 0);
            cp_async16(&Af[buf][r][kq * 4], gp, ok ? 16 : 0);
        }
#pragma unroll
        for (int it = 0; it < 4; it++) {
            int slot = it * 256 + tid;
            int kk = slot >> 5, cq = slot & 31;
            int gk = k0 + kk;
            int ok = (gk < D_IN);
            const float* gp = Wm + (size_t)(ok ? gk : 0) * D_OUT + cq * 4;
            cp_async16(&Bf[buf][kk][cq * 4], gp, ok ? 16 : 0);
        }
        asm volatile("cp.async.commit_group;\n");
    };

    load_chunk(0, 0);
    for (int c = 0; c < NCH; c++) {
        int buf = c & 1;
        if (c + 1 < NCH) {
            load_chunk((c + 1) * KCH, buf ^ 1);
            asm volatile("cp.async.wait_group 1;\n");
        } else {
            asm volatile("cp.async.wait_group 0;\n");
        }
        __syncthreads();

#pragma unroll
        for (int ks = 0; ks < KCH; ks += 8) {
            unsigned a[2][4], b[8][2];
#pragma unroll
            for (int mi = 0; mi < 2; mi++) {
                int r0 = wm * 32 + mi * 16 + g;
                a[mi][0] = f2tf32(Af[buf][r0][ks + tg]);
                a[mi][1] = f2tf32(Af[buf][r0 + 8][ks + tg]);
                a[mi][2] = f2tf32(Af[buf][r0][ks + tg + 4]);
                a[mi][3] = f2tf32(Af[buf][r0 + 8][ks + tg + 4]);
            }
#pragma unroll
            for (int ni = 0; ni < 8; ni++) {
                int n = wn * 64 + ni * 8 + g;
                b[ni][0] = f2tf32(Bf[buf][ks + tg][n]);
                b[ni][1] = f2tf32(Bf[buf][ks + tg + 4][n]);
            }
#pragma unroll
            for (int mi = 0; mi < 2; mi++)
#pragma unroll
                for (int ni = 0; ni < 8; ni++)
                    mma_tf32(acc[mi][ni], a[mi], b[ni]);
        }
        __syncthreads();
    }

#pragma unroll
    for (int mi = 0; mi < 2; mi++) {
        int r = row0 + wm * 32 + mi * 16 + g;
#pragma unroll
        for (int ni = 0; ni < 8; ni++) {
            int cb = wn * 64 + ni * 8 + tg * 2;
            float b0 = bias[cb], b1 = bias[cb + 1];
            if (r < M) {
                __half2 o = __floats2half2_rn(acc[mi][ni][0] + b0, acc[mi][ni][1] + b1);
                *(__half2*)(C + (size_t)r * D_OUT + cb) = o;
            }
            if (r + 8 < M) {
                __half2 o = __floats2half2_rn(acc[mi][ni][2] + b0, acc[mi][ni][3] + b1);
                *(__half2*)(C + (size_t)(r + 8) * D_OUT + cb) = o;
            }
        }
    }
}

// ---------------------------------------------------------------------------
// Aggregation helpers. Per-dst segment: [off[d*REP], off[d*REP + REP]).
// ---------------------------------------------------------------------------
__device__ __forceinline__ void seg_mean_acc(int et, int d, int lane, float4& res) {
    const int*    off = off_ptr(et);
    const uint2*  pp  = pair_ptr(et);
    const __half* Wh  = Wh_ptr(et);
    int beg = off[d * REP], end = off[d * REP + REP];
    float4 acc0 = make_float4(0.f, 0.f, 0.f, 0.f);
    float4 acc1 = make_float4(0.f, 0.f, 0.f, 0.f);
    int j = beg;
    for (; j + 4 <= end; j += 4) {
        uint2 p0 = __ldcs(pp + j),     p1 = __ldcs(pp + j + 1);
        uint2 p2 = __ldcs(pp + j + 2), p3 = __ldcs(pp + j + 3);
        float w0 = __uint_as_float(p0.y), w1 = __uint_as_float(p1.y);
        float w2 = __uint_as_float(p2.y), w3 = __uint_as_float(p3.y);
        float4 v0 = ldWh4(Wh, p0.x, lane);
        float4 v1 = ldWh4(Wh, p1.x, lane);
        float4 v2 = ldWh4(Wh, p2.x, lane);
        float4 v3 = ldWh4(Wh, p3.x, lane);
        acc0.x = fmaf(w0, v0.x, acc0.x); acc0.y = fmaf(w0, v0.y, acc0.y);
        acc0.z = fmaf(w0, v0.z, acc0.z); acc0.w = fmaf(w0, v0.w, acc0.w);
        acc1.x = fmaf(w1, v1.x, acc1.x); acc1.y = fmaf(w1, v1.y, acc1.y);
        acc1.z = fmaf(w1, v1.z, acc1.z); acc1.w = fmaf(w1, v1.w, acc1.w);
        acc0.x = fmaf(w2, v2.x, acc0.x); acc0.y = fmaf(w2, v2.y, acc0.y);
        acc0.z = fmaf(w2, v2.z, acc0.z); acc0.w = fmaf(w2, v2.w, acc0.w);
        acc1.x = fmaf(w3, v3.x, acc1.x); acc1.y = fmaf(w3, v3.y, acc1.y);
        acc1.z = fmaf(w3, v3.z, acc1.z); acc1.w = fmaf(w3, v3.w, acc1.w);
    }
    for (; j < end; j++) {
        uint2 p = __ldcs(pp + j);
        float w = __uint_as_float(p.y);
        float4 v = ldWh4(Wh, p.x, lane);
        acc0.x = fmaf(w, v.x, acc0.x); acc0.y = fmaf(w, v.y, acc0.y);
        acc0.z = fmaf(w, v.z, acc0.z); acc0.w = fmaf(w, v.w, acc0.w);
    }
    float inv = 1.0f / fmaxf((float)(end - beg), 1.0f);
    res.x += (acc0.x + acc1.x) * inv;
    res.y += (acc0.y + acc1.y) * inv;
    res.z += (acc0.z + acc1.z) * inv;
    res.w += (acc0.w + acc1.w) * inv;
}

// Kernel 6a: word nodes (needs Wh_ww only)
__global__ void agg_word_kernel(float* __restrict__ out) {
    int gw   = (blockIdx.x * blockDim.x + threadIdx.x) >> 5;
    int lane = threadIdx.x & 31;
    if (gw >= N_WORD) return;
    float4 res = make_float4(0.f, 0.f, 0.f, 0.f);
    seg_mean_acc(0, gw, lane, res);
    *(float4*)(out + (size_t)gw * D_OUT + lane * 4) = res;
}

// Kernel 6b: doc nodes (needs Wh_wd + Wh_td)
__global__ void agg_doc_kernel(float* __restrict__ out) {
    int d    = (blockIdx.x * blockDim.x + threadIdx.x) >> 5;
    int lane = threadIdx.x & 31;
    if (d >= N_DOC) return;
    float4 res = make_float4(0.f, 0.f, 0.f, 0.f);
    seg_mean_acc(2, d, lane, res);
    seg_mean_acc(3, d, lane, res);
    *(float4*)(out + (size_t)(N_WORD + N_TOPIC + d) * D_OUT + lane * 4) = res;
}

// Kernel 6c: topic nodes, block-per-node (long segments)
__global__ void __launch_bounds__(256) agg_topic_kernel(float* __restrict__ out) {
    __shared__ float4 sm[8][32];
    const int d    = blockIdx.x;
    const int lane = threadIdx.x & 31;
    const int wid  = threadIdx.x >> 5;
    float4 res = make_float4(0.f, 0.f, 0.f, 0.f);

#pragma unroll
    for (int pass = 0; pass < 2; pass++) {
        const int     et  = pass ? 4 : 1;
        const int*    off = off_ptr(et);
        const uint2*  pp  = pair_ptr(et);
        const __half* Wh  = Wh_ptr(et);
        int beg = off[d * REP], end = off[d * REP + REP];
        float4 acc = make_float4(0.f, 0.f, 0.f, 0.f);
        int j = beg + wid;
        for (; j + 8 < end; j += 16) {
            uint2 pA = __ldcs(pp + j), pB = __ldcs(pp + j + 8);
            float wA = __uint_as_float(pA.y), wB = __uint_as_float(pB.y);
            float4 vA = ldWh4(Wh, pA.x, lane);
            float4 vB = ldWh4(Wh, pB.x, lane);
            acc.x = fmaf(wA, vA.x, acc.x); acc.y = fmaf(wA, vA.y, acc.y);
            acc.z = fmaf(wA, vA.z, acc.z); acc.w = fmaf(wA, vA.w, acc.w);
            acc.x = fmaf(wB, vB.x, acc.x); acc.y = fmaf(wB, vB.y, acc.y);
            acc.z = fmaf(wB, vB.z, acc.z); acc.w = fmaf(wB, vB.w, acc.w);
        }
        if (j < end) {
            uint2 p = __ldcs(pp + j);
            float w = __uint_as_float(p.y);
            float4 v = ldWh4(Wh, p.x, lane);
            acc.x = fmaf(w, v.x, acc.x); acc.y = fmaf(w, v.y, acc.y);
            acc.z = fmaf(w, v.z, acc.z); acc.w = fmaf(w, v.w, acc.w);
        }
        sm[wid][lane] = acc;
        __syncthreads();
        if (wid == 0) {
            float4 s = sm[0][lane];
#pragma unroll
            for (int w2 = 1; w2 < 8; w2++) {
                float4 t = sm[w2][lane];
                s.x += t.x; s.y += t.y; s.z += t.z; s.w += t.w;
            }
            float inv = 1.0f / fmaxf((float)(end - beg), 1.0f);
            res.x += s.x * inv; res.y += s.y * inv;
            res.z += s.z * inv; res.w += s.w * inv;
        }
        __syncthreads();
    }
    if (wid == 0)
        *(float4*)(out + (size_t)(N_WORD + d) * D_OUT + lane * 4) = res;
}

// ---------------------------------------------------------------------------
// Launch: side: gemm_ww -> gemm_wdtd -> gemm_t -> agg_topic;
// main: CSR build -> agg_word (gated on gemm_ww) -> agg_doc (gated on wdtd).
// ---------------------------------------------------------------------------
extern "C" void kernel_launch(void* const* d_in, const int* in_sizes, int n_in,
                              void* d_out, int out_size) {
    (void)out_size;

    static cudaStream_t s_side = nullptr;
    static cudaEvent_t  ev_fork = nullptr, ev_ww = nullptr, ev_wdtd = nullptr,
                        ev_fill = nullptr, ev_side = nullptr;
    if (!s_side) {
        cudaStreamCreateWithFlags(&s_side, cudaStreamNonBlocking);
        cudaEventCreateWithFlags(&ev_fork, cudaEventDisableTiming);
        cudaEventCreateWithFlags(&ev_ww,   cudaEventDisableTiming);
        cudaEventCreateWithFlags(&ev_wdtd, cudaEventDisableTiming);
        cudaEventCreateWithFlags(&ev_fill, cudaEventDisableTiming);
        cudaEventCreateWithFlags(&ev_side, cudaEventDisableTiming);
    }

    // Resolve input ordering (W matrices are 38400 elems)
    int iS[5], iD[5], iW_[5], iWm[5], iB[5];
    bool interleaved = (n_in >= 7 && in_sizes[5] == D_IN * D_OUT);
    for (int et = 0; et < 5; et++) {
        if (interleaved) {
            int base = 2 + et * 5;
            iS[et] = base; iD[et] = base + 1; iW_[et] = base + 2;
            iWm[et] = base + 3; iB[et] = base + 4;
        } else {
            iS[et] = 2 + et * 3; iD[et] = 3 + et * 3; iW_[et] = 4 + et * 3;
            iWm[et] = 17 + et * 2; iB[et] = 18 + et * 2;
        }
    }

    EdgeArgs ea;
    GemmArgs ga;
    ga.featW = (const float*)d_in[0];
    ga.featT = (const float*)d_in[1];
    for (int et = 0; et < 5; et++) {
        ea.src[et]  = (const int*)d_in[iS[et]];
        ea.dst[et]  = (const int*)d_in[iD[et]];
        ea.w[et]    = (const float*)d_in[iW_[et]];
        ga.Wm[et]   = (const float*)d_in[iWm[et]];
        ga.bias[et] = (const float*)d_in[iB[et]];
    }
    float* out = (float*)d_out;

    // Fork: ww GEMM (gates agg_word), then wd+td, then wt+tt
    cudaEventRecord(ev_fork, 0);
    cudaStreamWaitEvent(s_side, ev_fork, 0);
    gemm_tf32_kernel<<<TILES_WW, 256, 0, s_side>>>(ga, 0);
    cudaEventRecord(ev_ww, s_side);
    gemm_tf32_kernel<<<TILES_WDTD, 256, 0, s_side>>>(ga, TILES_WW);
    cudaEventRecord(ev_wdtd, s_side);
    gemm_tf32_kernel<<<TILES_TOTAL - TILES_G2, 256, 0, s_side>>>(ga, TILES_G2);

    // Main stream: CSR build (deg zeroed by previous call's scan / module init)
    hist_all_kernel<<<(E_TOT / 4 + 255) / 256, 256>>>(ea);
    scan_all_kernel<<<5, 1024>>>();
    fill_all_kernel<<<(E_TOT / 4 + 255) / 256, 256>>>(ea);
    cudaEventRecord(ev_fill, 0);

    // Side stream: topic aggregation (after topic GEMM in-order; wait for fill)
    cudaStreamWaitEvent(s_side, ev_fill, 0);
    agg_topic_kernel<<<N_TOPIC, 256, 0, s_side>>>(out);
    cudaEventRecord(ev_side, s_side);

    // Main stream: word agg (gated on ww GEMM), then doc agg (gated on wd+td)
    cudaStreamWaitEvent(0, ev_ww, 0);
    agg_word_kernel<<<(N_WORD * 32 + 255) / 256, 256>>>(out);
    cudaStreamWaitEvent(0, ev_wdtd, 0);
    agg_doc_kernel<<<(N_DOC * 32 + 255) / 256, 256>>>(out);
    cudaStreamWaitEvent(0, ev_side, 0);
}

// round 17
// speedup vs baseline: 2.0142x; 2.0142x over previous
#include <cuda_runtime.h>
#include <cuda_fp16.h>
#include <cstdint>

// ---------------------------------------------------------------------------
// Problem constants
// ---------------------------------------------------------------------------
#define N_WORD   30000
#define N_TOPIC  1000
#define N_DOC    15000
#define D_IN     300
#define D_OUT    128

#define E_WW 800000
#define E_WT 400000
#define E_WD 600000
#define E_TD 300000
#define E_TT 150000
#define E_TOT (E_WW + E_WT + E_WD + E_TD + E_TT)   // 2,250,000
// etype ids: 0=ww, 1=wt, 2=wd, 3=td, 4=tt (all boundaries divisible by 4)

// Counter replication ONLY for topic-dst etypes (wt, tt) where per-address
// atomic contention is high (400 / 150 edges per counter). Word/doc etypes
// (27-60 edges/counter) keep REP=1, so their scan/fill/agg are unchanged.
#define REP_T 8
__device__ __forceinline__ int rep_of(int et) { return (et == 1 || et == 4) ? REP_T : 1; }

// GEMM tile bookkeeping. Tile order: ww(235) | wd(235), td(8) | wt(235), tt(8)
#define T_W  235
#define T_T  8
#define TILES_WW   T_W                              // 235
#define TILES_WDTD (T_W + T_T)                      // 243
#define TILES_G2   (TILES_WW + TILES_WDTD)          // 478
#define TILES_TOTAL (3 * T_W + 2 * T_T)             // 721
#define KCH  32
#define NCH  10

#define SCAN_SMEM (N_WORD * 4)                      // 120,000 B dynamic smem

// ---------------------------------------------------------------------------
// Static device scratch.  Wh in fp16 (agg math stays fp32).
// ---------------------------------------------------------------------------
__device__ __half g_Wh_ww[(size_t)N_WORD  * D_OUT];
__device__ __half g_Wh_wt[(size_t)N_WORD  * D_OUT];
__device__ __half g_Wh_wd[(size_t)N_WORD  * D_OUT];
__device__ __half g_Wh_td[(size_t)N_TOPIC * D_OUT];
__device__ __half g_Wh_tt[(size_t)N_TOPIC * D_OUT];

__device__ __align__(16) int g_deg_ww[N_WORD];          __device__ int g_off_ww[N_WORD + 1];
__device__ __align__(16) int g_deg_wt[N_TOPIC * REP_T]; __device__ int g_off_wt[N_TOPIC * REP_T + 1];
__device__ __align__(16) int g_deg_wd[N_DOC];           __device__ int g_off_wd[N_DOC + 1];
__device__ __align__(16) int g_deg_td[N_DOC];           __device__ int g_off_td[N_DOC + 1];
__device__ __align__(16) int g_deg_tt[N_TOPIC * REP_T]; __device__ int g_off_tt[N_TOPIC * REP_T + 1];

__device__ __align__(16) int g_rank[E_TOT];

__device__ uint2 g_pair_ww[E_WW];
__device__ uint2 g_pair_wt[E_WT];
__device__ uint2 g_pair_wd[E_WD];
__device__ uint2 g_pair_td[E_TD];
__device__ uint2 g_pair_tt[E_TT];

__device__ __forceinline__ __half* Wh_ptr(int et) {
    switch (et) { case 0: return g_Wh_ww; case 1: return g_Wh_wt; case 2: return g_Wh_wd;
                  case 3: return g_Wh_td; default: return g_Wh_tt; }
}
__device__ __forceinline__ int* deg_ptr(int et) {
    switch (et) { case 0: return g_deg_ww; case 1: return g_deg_wt; case 2: return g_deg_wd;
                  case 3: return g_deg_td; default: return g_deg_tt; }
}
__device__ __forceinline__ int* off_ptr(int et) {
    switch (et) { case 0: return g_off_ww; case 1: return g_off_wt; case 2: return g_off_wd;
                  case 3: return g_off_td; default: return g_off_tt; }
}
__device__ __forceinline__ uint2* pair_ptr(int et) {
    switch (et) { case 0: return g_pair_ww; case 1: return g_pair_wt; case 2: return g_pair_wd;
                  case 3: return g_pair_td; default: return g_pair_tt; }
}
__device__ __forceinline__ int ndst_of(int et) {
    switch (et) { case 0: return N_WORD; case 1: return N_TOPIC; case 2: return N_DOC;
                  case 3: return N_DOC; default: return N_TOPIC; }
}

__device__ __forceinline__ float4 ldWh4(const __half* Wh, unsigned src, int lane) {
    uint2 raw = *(const uint2*)(Wh + (size_t)src * D_OUT + lane * 4);
    __half2 h0 = *reinterpret_cast<__half2*>(&raw.x);
    __half2 h1 = *reinterpret_cast<__half2*>(&raw.y);
    float2 f0 = __half22float2(h0);
    float2 f1 = __half22float2(h1);
    return make_float4(f0.x, f0.y, f1.x, f1.y);
}

// ---------------------------------------------------------------------------
// Pointer bundles
// ---------------------------------------------------------------------------
struct EdgeArgs {
    const int*   src[5];
    const int*   dst[5];
    const float* w[5];
};
struct GemmArgs {
    const float* featW;
    const float* featT;
    const float* Wm[5];
    const float* bias[5];
};

__device__ __forceinline__ void edge_map(int i, int& et, int& j) {
    if (i < E_WW)                        { et = 0; j = i; }
    else if (i < E_WW + E_WT)            { et = 1; j = i - E_WW; }
    else if (i < E_WW + E_WT + E_WD)     { et = 2; j = i - (E_WW + E_WT); }
    else if (i < E_TOT - E_TT)           { et = 3; j = i - (E_WW + E_WT + E_WD); }
    else                                 { et = 4; j = i - (E_TOT - E_TT); }
}

// ---------------------------------------------------------------------------
// Kernel 2: fused histogram; replicated counters for topic-dst etypes.
// counter index = d * R + (gid & (R-1));  R=1 reduces to index d.
// deg[] zeroed by previous call's scan (module init on call 0).
// ---------------------------------------------------------------------------
__global__ void hist_all_kernel(EdgeArgs ea) {
    int gid = blockIdx.x * blockDim.x + threadIdx.x;
    int i4 = gid * 4;
    if (i4 >= E_TOT) return;
    int et, j; edge_map(i4, et, j);
    int R = rep_of(et);
    int rep = gid & (R - 1);
    int* deg = deg_ptr(et);
    int4 d4 = *(const int4*)(ea.dst[et] + j);
    int4 r4;
    r4.x = atomicAdd(&deg[d4.x * R + rep], 1);
    r4.y = atomicAdd(&deg[d4.y * R + rep], 1);
    r4.z = atomicAdd(&deg[d4.z * R + rep], 1);
    r4.w = atomicAdd(&deg[d4.w * R + rep], 1);
    *(int4*)(g_rank + i4) = r4;
}

// ---------------------------------------------------------------------------
// Kernel 3: fused scan, one block per etype, over n = ndst * rep_of entries
// (ww 30000, wt 8000, wd/td 15000, tt 8000). Phase 1 caches deg into smem
// and re-zeroes it; phase 2 reads smem only.
// ---------------------------------------------------------------------------
__global__ void scan_all_kernel() {
    extern __shared__ int sdeg[];
    const int et = blockIdx.x;
    const int n = ndst_of(et) * rep_of(et);
    int* deg = deg_ptr(et);
    int* off = off_ptr(et);
    __shared__ int warp_pre[32];
    __shared__ int s_total;

    const int t = threadIdx.x;
    const int lane = t & 31, wid = t >> 5;
    int chunk = (((n + 1023) >> 10) + 3) & ~3;
    int beg = t * chunk;
    int end = min(beg + chunk, n);

    // phase 1: load deg -> smem, zero deg, accumulate per-thread sum
    int s = 0;
    const int4 z4 = make_int4(0, 0, 0, 0);
    int i = beg;
    for (; i + 4 <= end; i += 4) {
        int4 v = *(const int4*)(deg + i);
        *(int4*)(sdeg + i) = v;
        *(int4*)(deg + i)  = z4;
        s += v.x + v.y + v.z + v.w;
    }
    for (; i < end; i++) { int v = deg[i]; sdeg[i] = v; deg[i] = 0; s += v; }

    // block scan of per-thread sums
    int inc = s;
#pragma unroll
    for (int d = 1; d < 32; d <<= 1) {
        int v = __shfl_up_sync(0xFFFFFFFFu, inc, d);
        if (lane >= d) inc += v;
    }
    if (lane == 31) warp_pre[wid] = inc;
    __syncthreads();
    if (wid == 0) {
        int ws = warp_pre[lane];
        int winc = ws;
#pragma unroll
        for (int d = 1; d < 32; d <<= 1) {
            int v = __shfl_up_sync(0xFFFFFFFFu, winc, d);
            if (lane >= d) winc += v;
        }
        warp_pre[lane] = winc - ws;
        if (lane == 31) s_total = winc;
    }
    __syncthreads();

    // phase 2: write offsets from smem-cached degrees
    int run = warp_pre[wid] + (inc - s);
    for (int j2 = beg; j2 < end; j2++) {
        off[j2] = run;
        run += sdeg[j2];
    }
    if (t == 0) off[n] = s_total;
}

// ---------------------------------------------------------------------------
// Kernel 4: atomic-free fill, 4 edges/thread; rep must match hist's rep
// ---------------------------------------------------------------------------
__global__ void fill_all_kernel(EdgeArgs ea) {
    int gid = blockIdx.x * blockDim.x + threadIdx.x;
    int i4 = gid * 4;
    if (i4 >= E_TOT) return;
    int et, j; edge_map(i4, et, j);
    int R = rep_of(et);
    int rep = gid & (R - 1);
    const int* off = off_ptr(et);
    uint2* pp = pair_ptr(et);
    int4   s4 = *(const int4*)(ea.src[et] + j);
    int4   d4 = *(const int4*)(ea.dst[et] + j);
    float4 w4 = *(const float4*)(ea.w[et] + j);
    int4   r4 = *(const int4*)(g_rank + i4);

    pp[off[d4.x * R + rep] + r4.x] = make_uint2((unsigned)s4.x, __float_as_uint(w4.x));
    pp[off[d4.y * R + rep] + r4.y] = make_uint2((unsigned)s4.y, __float_as_uint(w4.y));
    pp[off[d4.z * R + rep] + r4.z] = make_uint2((unsigned)s4.z, __float_as_uint(w4.z));
    pp[off[d4.w * R + rep] + r4.w] = make_uint2((unsigned)s4.w, __float_as_uint(w4.w));
}

// ---------------------------------------------------------------------------
// Kernel 5: tf32 GEMM, cp.async double-buffered, fp16 epilogue.
// Tile order: ww(0..234), wd(235..469), td(470..477), wt(478..712), tt(713..720)
// ---------------------------------------------------------------------------
__device__ __forceinline__ unsigned f2tf32(float x) {
    unsigned u; asm("cvt.rna.tf32.f32 %0, %1;" : "=r"(u) : "f"(x)); return u;
}
__device__ __forceinline__ void mma_tf32(float* c, const unsigned* a, const unsigned* b) {
    asm volatile(
        "mma.sync.aligned.m16n8k8.row.col.f32.tf32.tf32.f32 "
        "{%0,%1,%2,%3}, {%4,%5,%6,%7}, {%8,%9}, {%0,%1,%2,%3};\n"
        : "+f"(c[0]), "+f"(c[1]), "+f"(c[2]), "+f"(c[3])
        : "r"(a[0]), "r"(a[1]), "r"(a[2]), "r"(a[3]), "r"(b[0]), "r"(b[1]));
}
__device__ __forceinline__ void cp_async16(void* smem, const void* gmem, int valid_bytes) {
    unsigned sa = (unsigned)__cvta_generic_to_shared(smem);
    asm volatile("cp.async.cg.shared.global [%0], [%1], 16, %2;\n"
                 :: "r"(sa), "l"(gmem), "r"(valid_bytes));
}

__global__ void __launch_bounds__(256, 2)
gemm_tf32_kernel(GemmArgs ga, int bt0) {
    __shared__ float Af[2][128][36];
    __shared__ float Bf[2][32][136];

    int bt = blockIdx.x + bt0;
    int et, tile;
    if      (bt < T_W)                 { et = 0; tile = bt; }
    else if (bt < 2 * T_W)             { et = 2; tile = bt - T_W; }
    else if (bt < TILES_G2)            { et = 3; tile = bt - 2 * T_W; }
    else if (bt < TILES_G2 + T_W)      { et = 1; tile = bt - TILES_G2; }
    else                               { et = 4; tile = bt - (TILES_G2 + T_W); }

    const float* A    = (et < 3) ? ga.featW : ga.featT;
    const int    M    = (et < 3) ? N_WORD : N_TOPIC;
    const float* Wm   = ga.Wm[et];
    const float* bias = ga.bias[et];
    __half*      C    = Wh_ptr(et);

    const int row0 = tile * 128;
    const int tid  = threadIdx.x;
    const int lane = tid & 31, wid = tid >> 5;
    const int wm = wid & 3, wn = wid >> 2;
    const int g  = lane >> 2, tg = lane & 3;

    float acc[2][8][4];
#pragma unroll
    for (int mi = 0; mi < 2; mi++)
#pragma unroll
        for (int ni = 0; ni < 8; ni++)
#pragma unroll
            for (int q = 0; q < 4; q++) acc[mi][ni][q] = 0.0f;

    auto load_chunk = [&](int k0, int buf) {
#pragma unroll
        for (int it = 0; it < 4; it++) {
            int slot = it * 256 + tid;
            int r = slot >> 3, kq = slot & 7;
            int gr = row0 + r, gk = k0 + kq * 4;
            int ok = (gr < M && gk + 4 <= D_IN);
            const float* gp = A + (size_t)(ok ? gr : 0) * D_IN + (ok ? gk : 0);
            cp_async16(&Af[buf][r][kq * 4], gp, ok ? 16 : 0);
        }
#pragma unroll
        for (int it = 0; it < 4; it++) {
            int slot = it * 256 + tid;
            int kk = slot >> 5, cq = slot & 31;
            int gk = k0 + kk;
            int ok = (gk < D_IN);
            const float* gp = Wm + (size_t)(ok ? gk : 0) * D_OUT + cq * 4;
            cp_async16(&Bf[buf][kk][cq * 4], gp, ok ? 16 : 0);
        }
        asm volatile("cp.async.commit_group;\n");
    };

    load_chunk(0, 0);
    for (int c = 0; c < NCH; c++) {
        int buf = c & 1;
        if (c + 1 < NCH) {
            load_chunk((c + 1) * KCH, buf ^ 1);
            asm volatile("cp.async.wait_group 1;\n");
        } else {
            asm volatile("cp.async.wait_group 0;\n");
        }
        __syncthreads();

#pragma unroll
        for (int ks = 0; ks < KCH; ks += 8) {
            unsigned a[2][4], b[8][2];
#pragma unroll
            for (int mi = 0; mi < 2; mi++) {
                int r0 = wm * 32 + mi * 16 + g;
                a[mi][0] = f2tf32(Af[buf][r0][ks + tg]);
                a[mi][1] = f2tf32(Af[buf][r0 + 8][ks + tg]);
                a[mi][2] = f2tf32(Af[buf][r0][ks + tg + 4]);
                a[mi][3] = f2tf32(Af[buf][r0 + 8][ks + tg + 4]);
            }
#pragma unroll
            for (int ni = 0; ni < 8; ni++) {
                int n = wn * 64 + ni * 8 + g;
                b[ni][0] = f2tf32(Bf[buf][ks + tg][n]);
                b[ni][1] = f2tf32(Bf[buf][ks + tg + 4][n]);
            }
#pragma unroll
            for (int mi = 0; mi < 2; mi++)
#pragma unroll
                for (int ni = 0; ni < 8; ni++)
                    mma_tf32(acc[mi][ni], a[mi], b[ni]);
        }
        __syncthreads();
    }

#pragma unroll
    for (int mi = 0; mi < 2; mi++) {
        int r = row0 + wm * 32 + mi * 16 + g;
#pragma unroll
        for (int ni = 0; ni < 8; ni++) {
            int cb = wn * 64 + ni * 8 + tg * 2;
            float b0 = bias[cb], b1 = bias[cb + 1];
            if (r < M) {
                __half2 o = __floats2half2_rn(acc[mi][ni][0] + b0, acc[mi][ni][1] + b1);
                *(__half2*)(C + (size_t)r * D_OUT + cb) = o;
            }
            if (r + 8 < M) {
                __half2 o = __floats2half2_rn(acc[mi][ni][2] + b0, acc[mi][ni][3] + b1);
                *(__half2*)(C + (size_t)(r + 8) * D_OUT + cb) = o;
            }
        }
    }
}

// ---------------------------------------------------------------------------
// Aggregation helpers. REP=1 etypes: segment [off[d], off[d+1]).
// ---------------------------------------------------------------------------
__device__ __forceinline__ void seg_mean_acc(int et, int d, int lane, float4& res) {
    const int*    off = off_ptr(et);
    const uint2*  pp  = pair_ptr(et);
    const __half* Wh  = Wh_ptr(et);
    int beg = off[d], end = off[d + 1];
    float4 acc0 = make_float4(0.f, 0.f, 0.f, 0.f);
    float4 acc1 = make_float4(0.f, 0.f, 0.f, 0.f);
    int j = beg;
    for (; j + 4 <= end; j += 4) {
        uint2 p0 = __ldcs(pp + j),     p1 = __ldcs(pp + j + 1);
        uint2 p2 = __ldcs(pp + j + 2), p3 = __ldcs(pp + j + 3);
        float w0 = __uint_as_float(p0.y), w1 = __uint_as_float(p1.y);
        float w2 = __uint_as_float(p2.y), w3 = __uint_as_float(p3.y);
        float4 v0 = ldWh4(Wh, p0.x, lane);
        float4 v1 = ldWh4(Wh, p1.x, lane);
        float4 v2 = ldWh4(Wh, p2.x, lane);
        float4 v3 = ldWh4(Wh, p3.x, lane);
        acc0.x = fmaf(w0, v0.x, acc0.x); acc0.y = fmaf(w0, v0.y, acc0.y);
        acc0.z = fmaf(w0, v0.z, acc0.z); acc0.w = fmaf(w0, v0.w, acc0.w);
        acc1.x = fmaf(w1, v1.x, acc1.x); acc1.y = fmaf(w1, v1.y, acc1.y);
        acc1.z = fmaf(w1, v1.z, acc1.z); acc1.w = fmaf(w1, v1.w, acc1.w);
        acc0.x = fmaf(w2, v2.x, acc0.x); acc0.y = fmaf(w2, v2.y, acc0.y);
        acc0.z = fmaf(w2, v2.z, acc0.z); acc0.w = fmaf(w2, v2.w, acc0.w);
        acc1.x = fmaf(w3, v3.x, acc1.x); acc1.y = fmaf(w3, v3.y, acc1.y);
        acc1.z = fmaf(w3, v3.z, acc1.z); acc1.w = fmaf(w3, v3.w, acc1.w);
    }
    for (; j < end; j++) {
        uint2 p = __ldcs(pp + j);
        float w = __uint_as_float(p.y);
        float4 v = ldWh4(Wh, p.x, lane);
        acc0.x = fmaf(w, v.x, acc0.x); acc0.y = fmaf(w, v.y, acc0.y);
        acc0.z = fmaf(w, v.z, acc0.z); acc0.w = fmaf(w, v.w, acc0.w);
    }
    float inv = 1.0f / fmaxf((float)(end - beg), 1.0f);
    res.x += (acc0.x + acc1.x) * inv;
    res.y += (acc0.y + acc1.y) * inv;
    res.z += (acc0.z + acc1.z) * inv;
    res.w += (acc0.w + acc1.w) * inv;
}

// Kernel 6a: word nodes (needs Wh_ww only)
__global__ void agg_word_kernel(float* __restrict__ out) {
    int gw   = (blockIdx.x * blockDim.x + threadIdx.x) >> 5;
    int lane = threadIdx.x & 31;
    if (gw >= N_WORD) return;
    float4 res = make_float4(0.f, 0.f, 0.f, 0.f);
    seg_mean_acc(0, gw, lane, res);
    *(float4*)(out + (size_t)gw * D_OUT + lane * 4) = res;
}

// Kernel 6b: doc nodes (needs Wh_wd + Wh_td)
__global__ void agg_doc_kernel(float* __restrict__ out) {
    int d    = (blockIdx.x * blockDim.x + threadIdx.x) >> 5;
    int lane = threadIdx.x & 31;
    if (d >= N_DOC) return;
    float4 res = make_float4(0.f, 0.f, 0.f, 0.f);
    seg_mean_acc(2, d, lane, res);
    seg_mean_acc(3, d, lane, res);
    *(float4*)(out + (size_t)(N_WORD + N_TOPIC + d) * D_OUT + lane * 4) = res;
}

// Kernel 6c: topic nodes, block-per-node. Topic etypes are replicated:
// per-dst segment = [off[d*REP_T], off[d*REP_T + REP_T]) (contiguous).
__global__ void __launch_bounds__(256) agg_topic_kernel(float* __restrict__ out) {
    __shared__ float4 sm[8][32];
    const int d    = blockIdx.x;
    const int lane = threadIdx.x & 31;
    const int wid  = threadIdx.x >> 5;
    float4 res = make_float4(0.f, 0.f, 0.f, 0.f);

#pragma unroll
    for (int pass = 0; pass < 2; pass++) {
        const int     et  = pass ? 4 : 1;
        const int*    off = off_ptr(et);
        const uint2*  pp  = pair_ptr(et);
        const __half* Wh  = Wh_ptr(et);
        int beg = off[d * REP_T], end = off[d * REP_T + REP_T];
        float4 acc = make_float4(0.f, 0.f, 0.f, 0.f);
        int j = beg + wid;
        for (; j + 8 < end; j += 16) {
            uint2 pA = __ldcs(pp + j), pB = __ldcs(pp + j + 8);
            float wA = __uint_as_float(pA.y), wB = __uint_as_float(pB.y);
            float4 vA = ldWh4(Wh, pA.x, lane);
            float4 vB = ldWh4(Wh, pB.x, lane);
            acc.x = fmaf(wA, vA.x, acc.x); acc.y = fmaf(wA, vA.y, acc.y);
            acc.z = fmaf(wA, vA.z, acc.z); acc.w = fmaf(wA, vA.w, acc.w);
            acc.x = fmaf(wB, vB.x, acc.x); acc.y = fmaf(wB, vB.y, acc.y);
            acc.z = fmaf(wB, vB.z, acc.z); acc.w = fmaf(wB, vB.w, acc.w);
        }
        if (j < end) {
            uint2 p = __ldcs(pp + j);
            float w = __uint_as_float(p.y);
            float4 v = ldWh4(Wh, p.x, lane);
            acc.x = fmaf(w, v.x, acc.x); acc.y = fmaf(w, v.y, acc.y);
            acc.z = fmaf(w, v.z, acc.z); acc.w = fmaf(w, v.w, acc.w);
        }
        sm[wid][lane] = acc;
        __syncthreads();
        if (wid == 0) {
            float4 s = sm[0][lane];
#pragma unroll
            for (int w2 = 1; w2 < 8; w2++) {
                float4 t = sm[w2][lane];
                s.x += t.x; s.y += t.y; s.z += t.z; s.w += t.w;
            }
            float inv = 1.0f / fmaxf((float)(end - beg), 1.0f);
            res.x += s.x * inv; res.y += s.y * inv;
            res.z += s.z * inv; res.w += s.w * inv;
        }
        __syncthreads();
    }
    if (wid == 0)
        *(float4*)(out + (size_t)(N_WORD + d) * D_OUT + lane * 4) = res;
}

// ---------------------------------------------------------------------------
// Launch: side: gemm_ww -> gemm_wdtd -> gemm_t -> agg_topic;
// main: CSR build -> agg_word (gated on gemm_ww) -> agg_doc (gated on wdtd).
// ---------------------------------------------------------------------------
extern "C" void kernel_launch(void* const* d_in, const int* in_sizes, int n_in,
                              void* d_out, int out_size) {
    (void)out_size;

    static cudaStream_t s_side = nullptr;
    static cudaEvent_t  ev_fork = nullptr, ev_ww = nullptr, ev_wdtd = nullptr,
                        ev_fill = nullptr, ev_side = nullptr;
    if (!s_side) {
        cudaStreamCreateWithFlags(&s_side, cudaStreamNonBlocking);
        cudaEventCreateWithFlags(&ev_fork, cudaEventDisableTiming);
        cudaEventCreateWithFlags(&ev_ww,   cudaEventDisableTiming);
        cudaEventCreateWithFlags(&ev_wdtd, cudaEventDisableTiming);
        cudaEventCreateWithFlags(&ev_fill, cudaEventDisableTiming);
        cudaEventCreateWithFlags(&ev_side, cudaEventDisableTiming);
        cudaFuncSetAttribute(scan_all_kernel,
                             cudaFuncAttributeMaxDynamicSharedMemorySize, SCAN_SMEM);
    }

    // Resolve input ordering (W matrices are 38400 elems)
    int iS[5], iD[5], iW_[5], iWm[5], iB[5];
    bool interleaved = (n_in >= 7 && in_sizes[5] == D_IN * D_OUT);
    for (int et = 0; et < 5; et++) {
        if (interleaved) {
            int base = 2 + et * 5;
            iS[et] = base; iD[et] = base + 1; iW_[et] = base + 2;
            iWm[et] = base + 3; iB[et] = base + 4;
        } else {
            iS[et] = 2 + et * 3; iD[et] = 3 + et * 3; iW_[et] = 4 + et * 3;
            iWm[et] = 17 + et * 2; iB[et] = 18 + et * 2;
        }
    }

    EdgeArgs ea;
    GemmArgs ga;
    ga.featW = (const float*)d_in[0];
    ga.featT = (const float*)d_in[1];
    for (int et = 0; et < 5; et++) {
        ea.src[et]  = (const int*)d_in[iS[et]];
        ea.dst[et]  = (const int*)d_in[iD[et]];
        ea.w[et]    = (const float*)d_in[iW_[et]];
        ga.Wm[et]   = (const float*)d_in[iWm[et]];
        ga.bias[et] = (const float*)d_in[iB[et]];
    }
    float* out = (float*)d_out;

    // Fork: ww GEMM (gates agg_word), then wd+td, then wt+tt
    cudaEventRecord(ev_fork, 0);
    cudaStreamWaitEvent(s_side, ev_fork, 0);
    gemm_tf32_kernel<<<TILES_WW, 256, 0, s_side>>>(ga, 0);
    cudaEventRecord(ev_ww, s_side);
    gemm_tf32_kernel<<<TILES_WDTD, 256, 0, s_side>>>(ga, TILES_WW);
    cudaEventRecord(ev_wdtd, s_side);
    gemm_tf32_kernel<<<TILES_TOTAL - TILES_G2, 256, 0, s_side>>>(ga, TILES_G2);

    // Main stream: CSR build (deg zeroed by previous call's scan / module init)
    hist_all_kernel<<<(E_TOT / 4 + 255) / 256, 256>>>(ea);
    scan_all_kernel<<<5, 1024, SCAN_SMEM>>>();
    fill_all_kernel<<<(E_TOT / 4 + 255) / 256, 256>>>(ea);
    cudaEventRecord(ev_fill, 0);

    // Side stream: topic aggregation (after topic GEMM in-order; wait for fill)
    cudaStreamWaitEvent(s_side, ev_fill, 0);
    agg_topic_kernel<<<N_TOPIC, 256, 0, s_side>>>(out);
    cudaEventRecord(ev_side, s_side);

    // Main stream: word agg (gated on ww GEMM), then doc agg (gated on wd+td)
    cudaStreamWaitEvent(0, ev_ww, 0);
    agg_word_kernel<<<(N_WORD * 32 + 255) / 256, 256>>>(out);
    cudaStreamWaitEvent(0, ev_wdtd, 0);
    agg_doc_kernel<<<(N_DOC * 32 + 255) / 256, 256>>>(out);
    cudaStreamWaitEvent(0, ev_side, 0);
}